// round 2
// baseline (speedup 1.0000x reference)
#include <cuda_runtime.h>
#include <cstdint>

// BoundingBox: mask [N,1,H,W] fp32 -> bbox [N,4] (ymin, xmin, ymax, xmax)
// with hit = (v >= 0.5f). Output buffer dtype is FLOAT32 (metadata __output__),
// even though the reference computes int32 — round-1 rel_err=1.0 was the
// int-bits-read-as-float signature. Write float values.
//
// Reference semantics:
//   lo = first hit index, hi = last hit index + 1; if no hit: lo = 0, hi = full.
//
// Strategy: four independent edge-inward early-exit scans per image.
//   dir 0: ymin  scan rows    top -> bottom, result r      (default 0)
//   dir 1: xmin  scan columns left -> right, result c      (default 0)
//   dir 2: ymax  scan rows    bottom -> top, result r + 1  (default H)
//   dir 3: xmax  scan columns right -> left, result c + 1  (default W)
// Exact for arbitrary inputs; for dense random masks each scan terminates
// after one probe, reading ~2KB instead of 1MB per image.

#define BB_H 512
#define BB_W 512
#define BB_THRESH 0.5f

__global__ __launch_bounds__(512, 4)
void BoundingBox_2834678415682_kernel(const float* __restrict__ mask,
                                      float* __restrict__ out) {
    const int n   = blockIdx.y;
    const int dir = blockIdx.x;
    const int tid = threadIdx.x;

    const float* __restrict__ img = mask + (size_t)n * BB_H * BB_W;

    int result;

    if (dir == 0) {
        // ymin: first row with any hit (default 0)
        result = 0;
        for (int r = 0; r < BB_H; ++r) {
            int hit = (img[(size_t)r * BB_W + tid] >= BB_THRESH) ? 1 : 0;
            if (__syncthreads_or(hit)) { result = r; break; }
        }
        if (tid == 0) out[n * 4 + 0] = (float)result;
    } else if (dir == 1) {
        // xmin: first column with any hit (default 0)
        result = 0;
        for (int c = 0; c < BB_W; ++c) {
            int hit = (img[(size_t)tid * BB_W + c] >= BB_THRESH) ? 1 : 0;
            if (__syncthreads_or(hit)) { result = c; break; }
        }
        if (tid == 0) out[n * 4 + 1] = (float)result;
    } else if (dir == 2) {
        // ymax: last row with any hit, +1 (default H)
        result = BB_H;
        for (int r = BB_H - 1; r >= 0; --r) {
            int hit = (img[(size_t)r * BB_W + tid] >= BB_THRESH) ? 1 : 0;
            if (__syncthreads_or(hit)) { result = r + 1; break; }
        }
        if (tid == 0) out[n * 4 + 2] = (float)result;
    } else {
        // xmax: last column with any hit, +1 (default W)
        result = BB_W;
        for (int c = BB_W - 1; c >= 0; --c) {
            int hit = (img[(size_t)tid * BB_W + c] >= BB_THRESH) ? 1 : 0;
            if (__syncthreads_or(hit)) { result = c + 1; break; }
        }
        if (tid == 0) out[n * 4 + 3] = (float)result;
    }
}

extern "C" void kernel_launch(void* const* d_in, const int* in_sizes, int n_in,
                              void* d_out, int out_size) {
    const float* mask = (const float*)d_in[0];
    float* out = (float*)d_out;

    const int N = in_sizes[0] / (BB_H * BB_W);

    dim3 grid(4, N, 1);
    dim3 block(512, 1, 1);
    BoundingBox_2834678415682_kernel<<<grid, block>>>(mask, out);
}